// round 8
// baseline (speedup 1.0000x reference)
#include <cuda_runtime.h>
#include <cstdint>

#define H 128
#define MAX_N 50048

__device__ float g_zn[(size_t)MAX_N * H];   // normalized layer-2 output
__device__ float g_h [(size_t)MAX_N * H];   // layer-1 activations (scratch)

__device__ __forceinline__ uint32_t f2tf(float x) {
    uint32_t r; asm("cvt.rna.tf32.f32 %0, %1;" : "=r"(r) : "f"(x)); return r;
}

// m16n8k8 tf32 MMA, D accumulates in-place (fp32).
__device__ __forceinline__ void mma8(float* d, const uint32_t* a, const uint32_t* b) {
    asm volatile("mma.sync.aligned.m16n8k8.row.col.f32.tf32.tf32.f32 "
        "{%0,%1,%2,%3}, {%4,%5,%6,%7}, {%8,%9}, {%0,%1,%2,%3};"
        : "+f"(d[0]), "+f"(d[1]), "+f"(d[2]), "+f"(d[3])
        : "r"(a[0]), "r"(a[1]), "r"(a[2]), "r"(a[3]), "r"(b[0]), "r"(b[1]));
}

#define XPITCH 132   // 16-row X tile pitch (floats); banks = lane+8kt -> conflict-free

// ---------------------------------------------------------------------------
// One MLP layer via 3xTF32 mma.sync.  8 warps/CTA; warp owns 16 output cols;
// W hi/lo fragments live in registers for the whole kernel.
// MODE 0: Y = ELU(X@W^T + b)  -> g_h
// MODE 1: Y = rownorm(X@W^T + b) -> g_zn   (X = g_h)
// ---------------------------------------------------------------------------
template<int MODE>
__global__ __launch_bounds__(256, 1)
void mlp_phase(const float* __restrict__ Xin, const float* __restrict__ W,
               const float* __restrict__ bias, int N, int n_tiles)
{
    __shared__ float xs[16 * XPITCH];
    __shared__ float ssbuf[16];

    const float* X = (MODE == 0) ? Xin : g_h;
    float*       Y = (MODE == 0) ? g_h : g_zn;

    const int tid  = threadIdx.x;
    const int warp = tid >> 5, lane = tid & 31;
    const int qr = lane >> 2, qc = lane & 3;          // quad row / col

    // ---- Weight fragments (B, col-major K x N): held in registers ----
    uint32_t wH[16][2][2], wL[16][2][2];
    #pragma unroll
    for (int kt = 0; kt < 16; kt++)
        #pragma unroll
        for (int nt = 0; nt < 2; nt++) {
            int n = warp * 16 + nt * 8 + qr;
            float w0 = __ldg(W + n * H + kt * 8 + qc);
            float w1 = __ldg(W + n * H + kt * 8 + qc + 4);
            uint32_t h0 = f2tf(w0), h1 = f2tf(w1);
            wH[kt][nt][0] = h0; wH[kt][nt][1] = h1;
            wL[kt][nt][0] = f2tf(w0 - __uint_as_float(h0));
            wL[kt][nt][1] = f2tf(w1 - __uint_as_float(h1));
        }

    const float2 bv0 = __ldg((const float2*)(bias + warp * 16 + qc * 2));
    const float2 bv1 = __ldg((const float2*)(bias + warp * 16 + 8 + qc * 2));

    for (int tile = blockIdx.x; tile < n_tiles; tile += gridDim.x) {
        const int row0 = tile * 16;
        __syncthreads();                              // xs/ssbuf reuse guard
        for (int i = tid; i < 16 * 32; i += 256) {    // cooperative 16x128 load
            int r = i >> 5, c4 = i & 31;
            float4 v = make_float4(0.f, 0.f, 0.f, 0.f);
            if (row0 + r < N) v = *(const float4*)(X + (size_t)(row0 + r) * H + c4 * 4);
            *(float4*)(xs + r * XPITCH + c4 * 4) = v;
        }
        if (MODE == 1 && tid < 16) ssbuf[tid] = 0.f;
        __syncthreads();

        float acc0[4] = {0.f, 0.f, 0.f, 0.f};
        float acc1[4] = {0.f, 0.f, 0.f, 0.f};

        #pragma unroll
        for (int kt = 0; kt < 16; kt++) {
            // A fragment (16x8, row-major): a0(qr,qc) a1(qr+8,qc) a2(qr,qc+4) a3(qr+8,qc+4)
            float x0 = xs[qr       * XPITCH + kt * 8 + qc];
            float x1 = xs[(qr + 8) * XPITCH + kt * 8 + qc];
            float x2 = xs[qr       * XPITCH + kt * 8 + qc + 4];
            float x3 = xs[(qr + 8) * XPITCH + kt * 8 + qc + 4];
            uint32_t aH[4], aL[4];
            aH[0] = f2tf(x0); aH[1] = f2tf(x1); aH[2] = f2tf(x2); aH[3] = f2tf(x3);
            aL[0] = f2tf(x0 - __uint_as_float(aH[0]));
            aL[1] = f2tf(x1 - __uint_as_float(aH[1]));
            aL[2] = f2tf(x2 - __uint_as_float(aH[2]));
            aL[3] = f2tf(x3 - __uint_as_float(aH[3]));
            mma8(acc0, aH, wH[kt][0]);  mma8(acc1, aH, wH[kt][1]);
            mma8(acc0, aL, wH[kt][0]);  mma8(acc1, aL, wH[kt][1]);
            mma8(acc0, aH, wL[kt][0]);  mma8(acc1, aH, wL[kt][1]);
        }

        // C frag: c0/c1 = row qr cols 2qc,2qc+1 ; c2/c3 = row qr+8 same cols
        const int r_lo = row0 + qr, r_hi = row0 + qr + 8;
        const int c0 = warp * 16 + qc * 2, c1 = warp * 16 + 8 + qc * 2;
        float z00 = acc0[0] + bv0.x, z01 = acc0[1] + bv0.y;
        float z02 = acc0[2] + bv0.x, z03 = acc0[3] + bv0.y;
        float z10 = acc1[0] + bv1.x, z11 = acc1[1] + bv1.y;
        float z12 = acc1[2] + bv1.x, z13 = acc1[3] + bv1.y;

        if (MODE == 0) {
            float2 v;
            if (r_lo < N) {
                v.x = z00 > 0.f ? z00 : expm1f(z00);
                v.y = z01 > 0.f ? z01 : expm1f(z01);
                *(float2*)(Y + (size_t)r_lo * H + c0) = v;
                v.x = z10 > 0.f ? z10 : expm1f(z10);
                v.y = z11 > 0.f ? z11 : expm1f(z11);
                *(float2*)(Y + (size_t)r_lo * H + c1) = v;
            }
            if (r_hi < N) {
                v.x = z02 > 0.f ? z02 : expm1f(z02);
                v.y = z03 > 0.f ? z03 : expm1f(z03);
                *(float2*)(Y + (size_t)r_hi * H + c0) = v;
                v.x = z12 > 0.f ? z12 : expm1f(z12);
                v.y = z13 > 0.f ? z13 : expm1f(z13);
                *(float2*)(Y + (size_t)r_hi * H + c1) = v;
            }
        } else {
            float s_lo = z00*z00 + z01*z01 + z10*z10 + z11*z11;
            float s_hi = z02*z02 + z03*z03 + z12*z12 + z13*z13;
            s_lo += __shfl_xor_sync(0xFFFFFFFFu, s_lo, 1);
            s_lo += __shfl_xor_sync(0xFFFFFFFFu, s_lo, 2);
            s_hi += __shfl_xor_sync(0xFFFFFFFFu, s_hi, 1);
            s_hi += __shfl_xor_sync(0xFFFFFFFFu, s_hi, 2);
            if (qc == 0) {
                atomicAdd(&ssbuf[qr], s_lo);
                atomicAdd(&ssbuf[qr + 8], s_hi);
            }
            __syncthreads();
            float inv_lo = 1.0f / fmaxf(sqrtf(ssbuf[qr]),     1e-8f);
            float inv_hi = 1.0f / fmaxf(sqrtf(ssbuf[qr + 8]), 1e-8f);
            if (r_lo < N) {
                *(float2*)(Y + (size_t)r_lo * H + c0) = make_float2(z00 * inv_lo, z01 * inv_lo);
                *(float2*)(Y + (size_t)r_lo * H + c1) = make_float2(z10 * inv_lo, z11 * inv_lo);
            }
            if (r_hi < N) {
                *(float2*)(Y + (size_t)r_hi * H + c0) = make_float2(z02 * inv_hi, z03 * inv_hi);
                *(float2*)(Y + (size_t)r_hi * H + c1) = make_float2(z12 * inv_hi, z13 * inv_hi);
            }
        }
    }
}

// ---------------------------------------------------------------------------
// Kernel B: per-edge cosine. 4 edges/warp, 8 lanes/edge (46.8us, L2-resident).
// ---------------------------------------------------------------------------
__global__ __launch_bounds__(256)
void edge_cos_kernel(const int* __restrict__ ei,
                     float* __restrict__ out, int E, int N)
{
    int warp_id = (blockIdx.x * blockDim.x + threadIdx.x) >> 5;
    int lane = threadIdx.x & 31;
    int sub  = lane & 7;
    int eg   = lane >> 3;
    int e = warp_id * 4 + eg;
    bool valid = e < E;
    int ec = valid ? __ldg(ei + e) : 0;
    int er = valid ? __ldg(ei + E + e) : 0;
    ec = min(max(ec, 0), N - 1);
    er = min(max(er, 0), N - 1);

    const float4* pa = (const float4*)(g_zn + (size_t)ec * H);
    const float4* pb = (const float4*)(g_zn + (size_t)er * H);

    float4 a0 = pa[sub],      b0 = pb[sub];
    float4 a1 = pa[sub + 8],  b1 = pb[sub + 8];
    float4 a2 = pa[sub + 16], b2 = pb[sub + 16];
    float4 a3 = pa[sub + 24], b3 = pb[sub + 24];

    float s0 = a0.x*b0.x + a0.y*b0.y + a0.z*b0.z + a0.w*b0.w;
    float s1 = a1.x*b1.x + a1.y*b1.y + a1.z*b1.z + a1.w*b1.w;
    s0 += a2.x*b2.x + a2.y*b2.y + a2.z*b2.z + a2.w*b2.w;
    s1 += a3.x*b3.x + a3.y*b3.y + a3.z*b3.z + a3.w*b3.w;
    float s = s0 + s1;

    s += __shfl_xor_sync(0xFFFFFFFFu, s, 4);
    s += __shfl_xor_sync(0xFFFFFFFFu, s, 2);
    s += __shfl_xor_sync(0xFFFFFFFFu, s, 1);
    if (sub == 0 && valid) out[e] = s;
}

// ---------------------------------------------------------------------------
extern "C" void kernel_launch(void* const* d_in, const int* in_sizes, int n_in,
                              void* d_out, int out_size)
{
    const float* emb = (const float*)d_in[0];
    const int*   ei  = (const int*)d_in[1];
    const float* W1  = (const float*)d_in[2];
    const float* b1  = (const float*)d_in[3];
    const float* W2  = (const float*)d_in[4];
    const float* b2  = (const float*)d_in[5];
    float* out = (float*)d_out;

    int N = in_sizes[0] / H;
    int E = in_sizes[1] / 2;
    int n_tiles = (N + 15) / 16;
    int gridA = n_tiles < 148 ? n_tiles : 148;

    mlp_phase<0><<<gridA, 256>>>(emb, W1, b1, N, n_tiles);   // emb -> g_h
    mlp_phase<1><<<gridA, 256>>>(emb, W2, b2, N, n_tiles);   // g_h -> g_zn (Xin unused)

    int warps  = (E + 3) / 4;
    int blocks = (warps + 7) / 8;
    edge_cos_kernel<<<blocks, 256>>>(ei, out, E, N);
}

// round 11
// speedup vs baseline: 1.2533x; 1.2533x over previous
#include <cuda_runtime.h>
#include <cuda_fp16.h>
#include <cstdint>

#define H 128
#define MAX_N 50048

__device__ __half g_zn_h[(size_t)MAX_N * H];  // normalized layer-2 output (fp16)
__device__ float  g_h[(size_t)MAX_N * H];     // layer-1 activations (fp32 scratch)

__device__ __forceinline__ uint32_t f2tf(float x) {
    uint32_t r; asm("cvt.rna.tf32.f32 %0, %1;" : "=r"(r) : "f"(x)); return r;
}

// m16n8k8 tf32 MMA, D accumulates in-place (fp32).
__device__ __forceinline__ void mma8(float* d, const uint32_t* a, const uint32_t* b) {
    asm volatile("mma.sync.aligned.m16n8k8.row.col.f32.tf32.tf32.f32 "
        "{%0,%1,%2,%3}, {%4,%5,%6,%7}, {%8,%9}, {%0,%1,%2,%3};"
        : "+f"(d[0]), "+f"(d[1]), "+f"(d[2]), "+f"(d[3])
        : "r"(a[0]), "r"(a[1]), "r"(a[2]), "r"(a[3]), "r"(b[0]), "r"(b[1]));
}

#define XPITCH 132

// ---------------------------------------------------------------------------
// One MLP layer via 3xTF32 mma.sync (AH*WH + AL*WH + AH*WL, fp32 accum).
// 8 warps/CTA, warp owns 16 output cols. Weights held fp32 in regs (64);
// tf32 hi/lo B-fragments derived per k-step -> fits 128 regs -> 2 CTAs/SM.
// Separate accumulators per split pass -> 6 independent HMMA chains/warp.
// MODE 0: Y = ELU(X@W1^T + b1) -> g_h   (fp32)
// MODE 1: Y = rownorm(g_h@W2^T + b2) -> g_zn_h (fp16)
// ---------------------------------------------------------------------------
template<int MODE>
__global__ __launch_bounds__(256, 2)
void mlp_phase(const float* __restrict__ Xin, const float* __restrict__ W,
               const float* __restrict__ bias, int N, int n_tiles)
{
    __shared__ float xs[16 * XPITCH];
    __shared__ float ssbuf[16];

    const float* X = (MODE == 0) ? Xin : g_h;

    const int tid  = threadIdx.x;
    const int warp = tid >> 5, lane = tid & 31;
    const int qr = lane >> 2, qc = lane & 3;

    // ---- Weights fp32 in registers: wr0/wr1[kt][nt] = W[n][kt*8+qc(+4)] ----
    float wr0[16][2], wr1[16][2];
    #pragma unroll
    for (int kt = 0; kt < 16; kt++)
        #pragma unroll
        for (int nt = 0; nt < 2; nt++) {
            int n = warp * 16 + nt * 8 + qr;
            wr0[kt][nt] = __ldg(W + n * H + kt * 8 + qc);
            wr1[kt][nt] = __ldg(W + n * H + kt * 8 + qc + 4);
        }

    const float2 bv0 = __ldg((const float2*)(bias + warp * 16 + qc * 2));
    const float2 bv1 = __ldg((const float2*)(bias + warp * 16 + 8 + qc * 2));

    for (int tile = blockIdx.x; tile < n_tiles; tile += gridDim.x) {
        const int row0 = tile * 16;
        __syncthreads();
        for (int i = tid; i < 16 * 32; i += 256) {
            int r = i >> 5, c4 = i & 31;
            float4 v = make_float4(0.f, 0.f, 0.f, 0.f);
            if (row0 + r < N) v = *(const float4*)(X + (size_t)(row0 + r) * H + c4 * 4);
            *(float4*)(xs + r * XPITCH + c4 * 4) = v;
        }
        if (MODE == 1 && tid < 16) ssbuf[tid] = 0.f;
        __syncthreads();

        // 6 independent accumulator chains: [pass A/B/C][nt]
        float aA0[4] = {0,0,0,0}, aA1[4] = {0,0,0,0};
        float aB0[4] = {0,0,0,0}, aB1[4] = {0,0,0,0};
        float aC0[4] = {0,0,0,0}, aC1[4] = {0,0,0,0};

        #pragma unroll
        for (int kt = 0; kt < 16; kt++) {
            float x0 = xs[qr       * XPITCH + kt * 8 + qc];
            float x1 = xs[(qr + 8) * XPITCH + kt * 8 + qc];
            float x2 = xs[qr       * XPITCH + kt * 8 + qc + 4];
            float x3 = xs[(qr + 8) * XPITCH + kt * 8 + qc + 4];
            uint32_t aH[4], aL[4];
            aH[0] = f2tf(x0); aH[1] = f2tf(x1); aH[2] = f2tf(x2); aH[3] = f2tf(x3);
            aL[0] = f2tf(x0 - __uint_as_float(aH[0]));
            aL[1] = f2tf(x1 - __uint_as_float(aH[1]));
            aL[2] = f2tf(x2 - __uint_as_float(aH[2]));
            aL[3] = f2tf(x3 - __uint_as_float(aH[3]));

            uint32_t bH0[2], bH1[2], bL0[2], bL1[2];
            bH0[0] = f2tf(wr0[kt][0]); bH0[1] = f2tf(wr1[kt][0]);
            bH1[0] = f2tf(wr0[kt][1]); bH1[1] = f2tf(wr1[kt][1]);
            bL0[0] = f2tf(wr0[kt][0] - __uint_as_float(bH0[0]));
            bL0[1] = f2tf(wr1[kt][0] - __uint_as_float(bH0[1]));
            bL1[0] = f2tf(wr0[kt][1] - __uint_as_float(bH1[0]));
            bL1[1] = f2tf(wr1[kt][1] - __uint_as_float(bH1[1]));

            mma8(aA0, aH, bH0);  mma8(aA1, aH, bH1);
            mma8(aB0, aL, bH0);  mma8(aB1, aL, bH1);
            mma8(aC0, aH, bL0);  mma8(aC1, aH, bL1);
        }

        const int r_lo = row0 + qr, r_hi = row0 + qr + 8;
        const int c0 = warp * 16 + qc * 2, c1 = warp * 16 + 8 + qc * 2;
        float z00 = (aA0[0] + aB0[0]) + aC0[0] + bv0.x;
        float z01 = (aA0[1] + aB0[1]) + aC0[1] + bv0.y;
        float z02 = (aA0[2] + aB0[2]) + aC0[2] + bv0.x;
        float z03 = (aA0[3] + aB0[3]) + aC0[3] + bv0.y;
        float z10 = (aA1[0] + aB1[0]) + aC1[0] + bv1.x;
        float z11 = (aA1[1] + aB1[1]) + aC1[1] + bv1.y;
        float z12 = (aA1[2] + aB1[2]) + aC1[2] + bv1.x;
        float z13 = (aA1[3] + aB1[3]) + aC1[3] + bv1.y;

        if (MODE == 0) {
            float2 v;
            if (r_lo < N) {
                v.x = z00 > 0.f ? z00 : expm1f(z00);
                v.y = z01 > 0.f ? z01 : expm1f(z01);
                *(float2*)(g_h + (size_t)r_lo * H + c0) = v;
                v.x = z10 > 0.f ? z10 : expm1f(z10);
                v.y = z11 > 0.f ? z11 : expm1f(z11);
                *(float2*)(g_h + (size_t)r_lo * H + c1) = v;
            }
            if (r_hi < N) {
                v.x = z02 > 0.f ? z02 : expm1f(z02);
                v.y = z03 > 0.f ? z03 : expm1f(z03);
                *(float2*)(g_h + (size_t)r_hi * H + c0) = v;
                v.x = z12 > 0.f ? z12 : expm1f(z12);
                v.y = z13 > 0.f ? z13 : expm1f(z13);
                *(float2*)(g_h + (size_t)r_hi * H + c1) = v;
            }
        } else {
            float s_lo = z00*z00 + z01*z01 + z10*z10 + z11*z11;
            float s_hi = z02*z02 + z03*z03 + z12*z12 + z13*z13;
            s_lo += __shfl_xor_sync(0xFFFFFFFFu, s_lo, 1);
            s_lo += __shfl_xor_sync(0xFFFFFFFFu, s_lo, 2);
            s_hi += __shfl_xor_sync(0xFFFFFFFFu, s_hi, 1);
            s_hi += __shfl_xor_sync(0xFFFFFFFFu, s_hi, 2);
            if (qc == 0) {
                atomicAdd(&ssbuf[qr], s_lo);
                atomicAdd(&ssbuf[qr + 8], s_hi);
            }
            __syncthreads();
            float inv_lo = 1.0f / fmaxf(sqrtf(ssbuf[qr]),     1e-8f);
            float inv_hi = 1.0f / fmaxf(sqrtf(ssbuf[qr + 8]), 1e-8f);
            if (r_lo < N) {
                *(__half2*)(g_zn_h + (size_t)r_lo * H + c0) =
                    __floats2half2_rn(z00 * inv_lo, z01 * inv_lo);
                *(__half2*)(g_zn_h + (size_t)r_lo * H + c1) =
                    __floats2half2_rn(z10 * inv_lo, z11 * inv_lo);
            }
            if (r_hi < N) {
                *(__half2*)(g_zn_h + (size_t)r_hi * H + c0) =
                    __floats2half2_rn(z02 * inv_hi, z03 * inv_hi);
                *(__half2*)(g_zn_h + (size_t)r_hi * H + c1) =
                    __floats2half2_rn(z12 * inv_hi, z13 * inv_hi);
            }
        }
    }
}

// ---------------------------------------------------------------------------
// Kernel B: per-edge cosine over fp16 zn (256B/row -> half the L2 traffic).
// 4 edges/warp, 8 lanes/edge; per lane 2x uint4 per side; fp32 accumulate.
// ---------------------------------------------------------------------------
__device__ __forceinline__ float dot16(uint4 a, uint4 b) {
    const __half2* ah = (const __half2*)&a;
    const __half2* bh = (const __half2*)&b;
    float s = 0.f;
    #pragma unroll
    for (int i = 0; i < 4; i++) {
        float2 fa = __half22float2(ah[i]);
        float2 fb = __half22float2(bh[i]);
        s += fa.x * fb.x + fa.y * fb.y;
    }
    return s;
}

__global__ __launch_bounds__(256)
void edge_cos_kernel(const int* __restrict__ ei,
                     float* __restrict__ out, int E, int N)
{
    int warp_id = (blockIdx.x * blockDim.x + threadIdx.x) >> 5;
    int lane = threadIdx.x & 31;
    int sub  = lane & 7;
    int eg   = lane >> 3;
    int e = warp_id * 4 + eg;
    bool valid = e < E;
    int ec = valid ? __ldg(ei + e) : 0;
    int er = valid ? __ldg(ei + E + e) : 0;
    ec = min(max(ec, 0), N - 1);
    er = min(max(er, 0), N - 1);

    const uint4* pa = (const uint4*)(g_zn_h + (size_t)ec * H);
    const uint4* pb = (const uint4*)(g_zn_h + (size_t)er * H);

    uint4 a0 = pa[sub],     b0 = pb[sub];        // halves 0..7   of lane's chunk
    uint4 a1 = pa[sub + 8], b1 = pb[sub + 8];    // halves 64..71 offset region

    float s = dot16(a0, b0) + dot16(a1, b1);

    s += __shfl_xor_sync(0xFFFFFFFFu, s, 4);
    s += __shfl_xor_sync(0xFFFFFFFFu, s, 2);
    s += __shfl_xor_sync(0xFFFFFFFFu, s, 1);
    if (sub == 0 && valid) out[e] = s;
}

// ---------------------------------------------------------------------------
extern "C" void kernel_launch(void* const* d_in, const int* in_sizes, int n_in,
                              void* d_out, int out_size)
{
    const float* emb = (const float*)d_in[0];
    const int*   ei  = (const int*)d_in[1];
    const float* W1  = (const float*)d_in[2];
    const float* b1  = (const float*)d_in[3];
    const float* W2  = (const float*)d_in[4];
    const float* b2  = (const float*)d_in[5];
    float* out = (float*)d_out;

    int N = in_sizes[0] / H;
    int E = in_sizes[1] / 2;
    int n_tiles = (N + 15) / 16;
    int gridA = n_tiles < 296 ? n_tiles : 296;   // 2 CTAs/SM

    mlp_phase<0><<<gridA, 256>>>(emb, W1, b1, N, n_tiles);
    mlp_phase<1><<<gridA, 256>>>(emb, W2, b2, N, n_tiles);

    int warps  = (E + 3) / 4;
    int blocks = (warps + 7) / 8;
    edge_cos_kernel<<<blocks, 256>>>(ei, out, E, N);
}

// round 12
// speedup vs baseline: 1.2878x; 1.0275x over previous
#include <cuda_runtime.h>
#include <cuda_fp16.h>
#include <cstdint>

#define H 128
#define MAX_N 50048

__device__ __half g_zn_h[(size_t)MAX_N * H];  // normalized layer-2 output (fp16)
__device__ float  g_h[(size_t)MAX_N * H];     // layer-1 activations (fp32 scratch)

__device__ __forceinline__ uint32_t f2tf(float x) {
    uint32_t r; asm("cvt.rna.tf32.f32 %0, %1;" : "=r"(r) : "f"(x)); return r;
}

// m16n8k8 tf32 MMA, D accumulates in-place (fp32).
__device__ __forceinline__ void mma8(float* d, const uint32_t* a, const uint32_t* b) {
    asm volatile("mma.sync.aligned.m16n8k8.row.col.f32.tf32.tf32.f32 "
        "{%0,%1,%2,%3}, {%4,%5,%6,%7}, {%8,%9}, {%0,%1,%2,%3};"
        : "+f"(d[0]), "+f"(d[1]), "+f"(d[2]), "+f"(d[3])
        : "r"(a[0]), "r"(a[1]), "r"(a[2]), "r"(a[3]), "r"(b[0]), "r"(b[1]));
}

#define XPITCH 132   // bank = 4*qr + 8*kt + qc -> 32 distinct banks per access

// ---------------------------------------------------------------------------
// One MLP layer via 3xTF32 mma.sync (AH*WH + AL*WH + AH*WL, fp32 accum).
// 512 threads / 16 warps, 1 CTA/SM. Warp owns 8 output cols (B hi/lo frags in
// 64 regs). A pre-split ONCE per CTA into xsH/xsL smem -> mainloop has ZERO
// cvt instructions: 8x LDS.32 + 3x MMA per k-step. 3 independent MMA chains.
// MODE 0: Y = ELU(X@W1^T + b1) -> g_h   (fp32)
// MODE 1: Y = rownorm(X@W2^T + b2) -> g_zn_h (fp16), X = g_h
// ---------------------------------------------------------------------------
template<int MODE>
__global__ __launch_bounds__(512, 1)
void mlp_phase(const float* __restrict__ Xin, const float* __restrict__ W,
               const float* __restrict__ bias, int N, int n_tiles)
{
    __shared__ uint32_t xsH[16 * XPITCH];
    __shared__ uint32_t xsL[16 * XPITCH];
    __shared__ float ssbuf[16];

    const float* X = (MODE == 0) ? Xin : g_h;

    const int tid  = threadIdx.x;
    const int warp = tid >> 5, lane = tid & 31;
    const int qr = lane >> 2, qc = lane & 3;

    // ---- B fragments (warp's 8 cols), tf32 hi/lo, in registers ----
    uint32_t bH[16][2], bL[16][2];
    {
        const int n = warp * 8 + qr;
        #pragma unroll
        for (int kt = 0; kt < 16; kt++) {
            float w0 = __ldg(W + n * H + kt * 8 + qc);
            float w1 = __ldg(W + n * H + kt * 8 + qc + 4);
            bH[kt][0] = f2tf(w0); bH[kt][1] = f2tf(w1);
            bL[kt][0] = f2tf(w0 - __uint_as_float(bH[kt][0]));
            bL[kt][1] = f2tf(w1 - __uint_as_float(bH[kt][1]));
        }
    }
    const float2 bv = __ldg((const float2*)(bias + warp * 8 + qc * 2));

    for (int tile = blockIdx.x; tile < n_tiles; tile += gridDim.x) {
        const int row0 = tile * 16;
        __syncthreads();
        {   // cooperative load + split: one float4 per thread
            int r = tid >> 5, c4 = tid & 31;
            float4 v = make_float4(0.f, 0.f, 0.f, 0.f);
            if (row0 + r < N) v = *(const float4*)(X + (size_t)(row0 + r) * H + c4 * 4);
            uint32_t h0 = f2tf(v.x), h1 = f2tf(v.y), h2 = f2tf(v.z), h3 = f2tf(v.w);
            uint32_t* dh = xsH + r * XPITCH + c4 * 4;
            uint32_t* dl = xsL + r * XPITCH + c4 * 4;
            dh[0] = h0; dh[1] = h1; dh[2] = h2; dh[3] = h3;
            dl[0] = f2tf(v.x - __uint_as_float(h0));
            dl[1] = f2tf(v.y - __uint_as_float(h1));
            dl[2] = f2tf(v.z - __uint_as_float(h2));
            dl[3] = f2tf(v.w - __uint_as_float(h3));
        }
        if (MODE == 1 && tid < 16) ssbuf[tid] = 0.f;
        __syncthreads();

        // 3 independent accumulator chains (one per split pass)
        float aA[4] = {0,0,0,0}, aB[4] = {0,0,0,0}, aC[4] = {0,0,0,0};

        const uint32_t* hlo = xsH + qr * XPITCH + qc;
        const uint32_t* hhi = xsH + (qr + 8) * XPITCH + qc;
        const uint32_t* llo = xsL + qr * XPITCH + qc;
        const uint32_t* lhi = xsL + (qr + 8) * XPITCH + qc;

        #pragma unroll
        for (int kt = 0; kt < 16; kt++) {
            uint32_t aHf[4], aLf[4];
            aHf[0] = hlo[kt * 8];     aHf[1] = hhi[kt * 8];
            aHf[2] = hlo[kt * 8 + 4]; aHf[3] = hhi[kt * 8 + 4];
            aLf[0] = llo[kt * 8];     aLf[1] = lhi[kt * 8];
            aLf[2] = llo[kt * 8 + 4]; aLf[3] = lhi[kt * 8 + 4];
            mma8(aA, aHf, bH[kt]);
            mma8(aB, aLf, bH[kt]);
            mma8(aC, aHf, bL[kt]);
        }

        const int r_lo = row0 + qr, r_hi = row0 + qr + 8;
        const int c0 = warp * 8 + qc * 2;
        float z00 = (aA[0] + aB[0]) + aC[0] + bv.x;
        float z01 = (aA[1] + aB[1]) + aC[1] + bv.y;
        float z02 = (aA[2] + aB[2]) + aC[2] + bv.x;
        float z03 = (aA[3] + aB[3]) + aC[3] + bv.y;

        if (MODE == 0) {
            float2 v;
            if (r_lo < N) {
                v.x = z00 > 0.f ? z00 : expm1f(z00);
                v.y = z01 > 0.f ? z01 : expm1f(z01);
                *(float2*)(g_h + (size_t)r_lo * H + c0) = v;
            }
            if (r_hi < N) {
                v.x = z02 > 0.f ? z02 : expm1f(z02);
                v.y = z03 > 0.f ? z03 : expm1f(z03);
                *(float2*)(g_h + (size_t)r_hi * H + c0) = v;
            }
        } else {
            float s_lo = z00 * z00 + z01 * z01;
            float s_hi = z02 * z02 + z03 * z03;
            s_lo += __shfl_xor_sync(0xFFFFFFFFu, s_lo, 1);
            s_lo += __shfl_xor_sync(0xFFFFFFFFu, s_lo, 2);
            s_hi += __shfl_xor_sync(0xFFFFFFFFu, s_hi, 1);
            s_hi += __shfl_xor_sync(0xFFFFFFFFu, s_hi, 2);
            if (qc == 0) {
                atomicAdd(&ssbuf[qr], s_lo);
                atomicAdd(&ssbuf[qr + 8], s_hi);
            }
            __syncthreads();
            float inv_lo = 1.0f / fmaxf(sqrtf(ssbuf[qr]),     1e-8f);
            float inv_hi = 1.0f / fmaxf(sqrtf(ssbuf[qr + 8]), 1e-8f);
            if (r_lo < N)
                *(__half2*)(g_zn_h + (size_t)r_lo * H + c0) =
                    __floats2half2_rn(z00 * inv_lo, z01 * inv_lo);
            if (r_hi < N)
                *(__half2*)(g_zn_h + (size_t)r_hi * H + c0) =
                    __floats2half2_rn(z02 * inv_hi, z03 * inv_hi);
        }
    }
}

// ---------------------------------------------------------------------------
// Kernel B: per-edge cosine over fp16 zn. 4 edges/warp, 8 lanes/edge.
// ---------------------------------------------------------------------------
__device__ __forceinline__ float dot16(uint4 a, uint4 b) {
    const __half2* ah = (const __half2*)&a;
    const __half2* bh = (const __half2*)&b;
    float s = 0.f;
    #pragma unroll
    for (int i = 0; i < 4; i++) {
        float2 fa = __half22float2(ah[i]);
        float2 fb = __half22float2(bh[i]);
        s += fa.x * fb.x + fa.y * fb.y;
    }
    return s;
}

__global__ __launch_bounds__(256)
void edge_cos_kernel(const int* __restrict__ ei,
                     float* __restrict__ out, int E, int N)
{
    int warp_id = (blockIdx.x * blockDim.x + threadIdx.x) >> 5;
    int lane = threadIdx.x & 31;
    int sub  = lane & 7;
    int eg   = lane >> 3;
    int e = warp_id * 4 + eg;
    bool valid = e < E;
    int ec = valid ? __ldg(ei + e) : 0;
    int er = valid ? __ldg(ei + E + e) : 0;
    ec = min(max(ec, 0), N - 1);
    er = min(max(er, 0), N - 1);

    const uint4* pa = (const uint4*)(g_zn_h + (size_t)ec * H);
    const uint4* pb = (const uint4*)(g_zn_h + (size_t)er * H);

    uint4 a0 = pa[sub],     b0 = pb[sub];
    uint4 a1 = pa[sub + 8], b1 = pb[sub + 8];

    float s = dot16(a0, b0) + dot16(a1, b1);

    s += __shfl_xor_sync(0xFFFFFFFFu, s, 4);
    s += __shfl_xor_sync(0xFFFFFFFFu, s, 2);
    s += __shfl_xor_sync(0xFFFFFFFFu, s, 1);
    if (sub == 0 && valid) out[e] = s;
}

// ---------------------------------------------------------------------------
extern "C" void kernel_launch(void* const* d_in, const int* in_sizes, int n_in,
                              void* d_out, int out_size)
{
    const float* emb = (const float*)d_in[0];
    const int*   ei  = (const int*)d_in[1];
    const float* W1  = (const float*)d_in[2];
    const float* b1  = (const float*)d_in[3];
    const float* W2  = (const float*)d_in[4];
    const float* b2  = (const float*)d_in[5];
    float* out = (float*)d_out;

    int N = in_sizes[0] / H;
    int E = in_sizes[1] / 2;
    int n_tiles = (N + 15) / 16;
    int gridA = n_tiles < 148 ? n_tiles : 148;

    mlp_phase<0><<<gridA, 512>>>(emb, W1, b1, N, n_tiles);
    mlp_phase<1><<<gridA, 512>>>(emb, W2, b2, N, n_tiles);

    int warps  = (E + 3) / 4;
    int blocks = (warps + 7) / 8;
    edge_cos_kernel<<<blocks, 256>>>(ei, out, E, N);
}

// round 13
// speedup vs baseline: 1.8997x; 1.4751x over previous
#include <cuda_runtime.h>
#include <cuda_fp16.h>
#include <cstdint>

#define H 128
#define MAX_N 50048

__device__ __half g_zn_h[(size_t)MAX_N * H];  // normalized layer-2 output (fp16)
__device__ float  g_h[(size_t)MAX_N * H];     // layer-1 activations (fp32 scratch)

// m16n8k16 fp16 MMA, fp32 accumulate in-place.
__device__ __forceinline__ void mma16(float* d, const uint32_t* a, const uint32_t* b) {
    asm volatile("mma.sync.aligned.m16n8k16.row.col.f32.f16.f16.f32 "
        "{%0,%1,%2,%3}, {%4,%5,%6,%7}, {%8,%9}, {%0,%1,%2,%3};"
        : "+f"(d[0]), "+f"(d[1]), "+f"(d[2]), "+f"(d[3])
        : "r"(a[0]), "r"(a[1]), "r"(a[2]), "r"(a[3]), "r"(b[0]), "r"(b[1]));
}

__device__ __forceinline__ uint32_t packh2(__half lo, __half hi) {
    __half2 h = __halves2half2(lo, hi);
    return *(uint32_t*)&h;
}

#define XP 68   // uint32 pitch per row (136 halves); word bank = 68r+qc -> 4r+qc distinct

// ---------------------------------------------------------------------------
// One MLP layer via 3xFP16 split mma.sync (xH*wH + xL*wH + xH*wL, fp32 accum).
// fp16 x fp16 products are EXACT in fp32; dropped xL*wL term ~2^-22 relative.
// CTA: 512 thr / 16 warps; tile 32 rows x 128 cols; warp (rh, cw) owns
// 16-row half rh and 16 cols. A pre-split once/CTA into fp16 hi/lo smem.
// Mainloop per warp: 8 kt x (8 LDS.32 + 6 MMA), zero cvt.
// MODE 0: Y = ELU(X@W1^T + b1) -> g_h (fp32)
// MODE 1: Y = rownorm(X@W2^T + b2) -> g_zn_h (fp16), X = g_h
// ---------------------------------------------------------------------------
template<int MODE>
__global__ __launch_bounds__(512, 1)
void mlp_phase(const float* __restrict__ Xin, const float* __restrict__ W,
               const float* __restrict__ bias, int N, int n_tiles)
{
    __shared__ uint32_t xsH[32 * XP];
    __shared__ uint32_t xsL[32 * XP];
    __shared__ float ssbuf[32];

    const float* X = (MODE == 0) ? Xin : g_h;

    const int tid  = threadIdx.x;
    const int warp = tid >> 5, lane = tid & 31;
    const int qr = lane >> 2, qc = lane & 3;
    const int rh = warp >> 3;          // row half (0/1)
    const int cw = warp & 7;           // column group (16 cols each)

    // ---- B fragments: warp's 16 cols, fp16 hi/lo, in registers (64 regs) ----
    uint32_t bH[8][2][2], bL[8][2][2];
    #pragma unroll
    for (int kt = 0; kt < 8; kt++)
        #pragma unroll
        for (int nt = 0; nt < 2; nt++) {
            const int n = cw * 16 + nt * 8 + qr;
            const float* wp = W + n * H + kt * 16 + 2 * qc;
            float w0 = __ldg(wp),     w1 = __ldg(wp + 1);
            float w2 = __ldg(wp + 8), w3 = __ldg(wp + 9);
            __half h0 = __float2half_rn(w0), h1 = __float2half_rn(w1);
            __half h2 = __float2half_rn(w2), h3 = __float2half_rn(w3);
            bH[kt][nt][0] = packh2(h0, h1);
            bH[kt][nt][1] = packh2(h2, h3);
            bL[kt][nt][0] = packh2(__float2half_rn(w0 - __half2float(h0)),
                                   __float2half_rn(w1 - __half2float(h1)));
            bL[kt][nt][1] = packh2(__float2half_rn(w2 - __half2float(h2)),
                                   __float2half_rn(w3 - __half2float(h3)));
        }

    const float2 bv0 = __ldg((const float2*)(bias + cw * 16 + 2 * qc));
    const float2 bv1 = __ldg((const float2*)(bias + cw * 16 + 8 + 2 * qc));

    for (int tile = blockIdx.x; tile < n_tiles; tile += gridDim.x) {
        const int row0 = tile * 32;
        __syncthreads();
        // ---- cooperative load + fp16 hi/lo split: 32 rows x 128 cols ----
        #pragma unroll
        for (int it = 0; it < 2; it++) {
            int i = tid + it * 512;
            int r = i >> 5, c4 = i & 31;          // c4: float4 chunk (4 cols)
            float4 v = make_float4(0.f, 0.f, 0.f, 0.f);
            if (row0 + r < N) v = *(const float4*)(X + (size_t)(row0 + r) * H + c4 * 4);
            __half h0 = __float2half_rn(v.x), h1 = __float2half_rn(v.y);
            __half h2 = __float2half_rn(v.z), h3 = __float2half_rn(v.w);
            uint32_t* dh = xsH + r * XP + c4 * 2;
            uint32_t* dl = xsL + r * XP + c4 * 2;
            dh[0] = packh2(h0, h1); dh[1] = packh2(h2, h3);
            dl[0] = packh2(__float2half_rn(v.x - __half2float(h0)),
                           __float2half_rn(v.y - __half2float(h1)));
            dl[1] = packh2(__float2half_rn(v.z - __half2float(h2)),
                           __float2half_rn(v.w - __half2float(h3)));
        }
        if (MODE == 1 && tid < 32) ssbuf[tid] = 0.f;
        __syncthreads();

        // 6 accumulator chains: [pass A/B/C][nt]
        float aA0[4] = {0,0,0,0}, aA1[4] = {0,0,0,0};
        float aB0[4] = {0,0,0,0}, aB1[4] = {0,0,0,0};
        float aC0[4] = {0,0,0,0}, aC1[4] = {0,0,0,0};

        // A frag words: row (rh*16 + qr [+8]), k word offset kt*8 + qc [+4]
        const uint32_t* hlo = xsH + (rh * 16 + qr) * XP + qc;
        const uint32_t* hhi = hlo + 8 * XP;
        const uint32_t* llo = xsL + (rh * 16 + qr) * XP + qc;
        const uint32_t* lhi = llo + 8 * XP;

        #pragma unroll
        for (int kt = 0; kt < 8; kt++) {
            uint32_t aH[4], aL[4];
            aH[0] = hlo[kt * 8];     aH[1] = hhi[kt * 8];
            aH[2] = hlo[kt * 8 + 4]; aH[3] = hhi[kt * 8 + 4];
            aL[0] = llo[kt * 8];     aL[1] = lhi[kt * 8];
            aL[2] = llo[kt * 8 + 4]; aL[3] = lhi[kt * 8 + 4];
            mma16(aA0, aH, bH[kt][0]);  mma16(aA1, aH, bH[kt][1]);
            mma16(aB0, aL, bH[kt][0]);  mma16(aB1, aL, bH[kt][1]);
            mma16(aC0, aH, bL[kt][0]);  mma16(aC1, aH, bL[kt][1]);
        }

        const int r_lo = row0 + rh * 16 + qr, r_hi = r_lo + 8;
        const int c0 = cw * 16 + 2 * qc, c1 = cw * 16 + 8 + 2 * qc;
        float z00 = (aA0[0] + aB0[0]) + aC0[0] + bv0.x;
        float z01 = (aA0[1] + aB0[1]) + aC0[1] + bv0.y;
        float z02 = (aA0[2] + aB0[2]) + aC0[2] + bv0.x;
        float z03 = (aA0[3] + aB0[3]) + aC0[3] + bv0.y;
        float z10 = (aA1[0] + aB1[0]) + aC1[0] + bv1.x;
        float z11 = (aA1[1] + aB1[1]) + aC1[1] + bv1.y;
        float z12 = (aA1[2] + aB1[2]) + aC1[2] + bv1.x;
        float z13 = (aA1[3] + aB1[3]) + aC1[3] + bv1.y;

        if (MODE == 0) {
            float2 v;
            if (r_lo < N) {
                v.x = z00 > 0.f ? z00 : expm1f(z00);
                v.y = z01 > 0.f ? z01 : expm1f(z01);
                *(float2*)(g_h + (size_t)r_lo * H + c0) = v;
                v.x = z10 > 0.f ? z10 : expm1f(z10);
                v.y = z11 > 0.f ? z11 : expm1f(z11);
                *(float2*)(g_h + (size_t)r_lo * H + c1) = v;
            }
            if (r_hi < N) {
                v.x = z02 > 0.f ? z02 : expm1f(z02);
                v.y = z03 > 0.f ? z03 : expm1f(z03);
                *(float2*)(g_h + (size_t)r_hi * H + c0) = v;
                v.x = z12 > 0.f ? z12 : expm1f(z12);
                v.y = z13 > 0.f ? z13 : expm1f(z13);
                *(float2*)(g_h + (size_t)r_hi * H + c1) = v;
            }
        } else {
            float s_lo = z00*z00 + z01*z01 + z10*z10 + z11*z11;
            float s_hi = z02*z02 + z03*z03 + z12*z12 + z13*z13;
            s_lo += __shfl_xor_sync(0xFFFFFFFFu, s_lo, 1);
            s_lo += __shfl_xor_sync(0xFFFFFFFFu, s_lo, 2);
            s_hi += __shfl_xor_sync(0xFFFFFFFFu, s_hi, 1);
            s_hi += __shfl_xor_sync(0xFFFFFFFFu, s_hi, 2);
            if (qc == 0) {
                atomicAdd(&ssbuf[rh * 16 + qr], s_lo);
                atomicAdd(&ssbuf[rh * 16 + qr + 8], s_hi);
            }
            __syncthreads();
            float inv_lo = 1.0f / fmaxf(sqrtf(ssbuf[rh * 16 + qr]),     1e-8f);
            float inv_hi = 1.0f / fmaxf(sqrtf(ssbuf[rh * 16 + qr + 8]), 1e-8f);
            if (r_lo < N) {
                *(__half2*)(g_zn_h + (size_t)r_lo * H + c0) =
                    __floats2half2_rn(z00 * inv_lo, z01 * inv_lo);
                *(__half2*)(g_zn_h + (size_t)r_lo * H + c1) =
                    __floats2half2_rn(z10 * inv_lo, z11 * inv_lo);
            }
            if (r_hi < N) {
                *(__half2*)(g_zn_h + (size_t)r_hi * H + c0) =
                    __floats2half2_rn(z02 * inv_hi, z03 * inv_hi);
                *(__half2*)(g_zn_h + (size_t)r_hi * H + c1) =
                    __floats2half2_rn(z12 * inv_hi, z13 * inv_hi);
            }
        }
    }
}

// ---------------------------------------------------------------------------
// Kernel B: per-edge cosine over fp16 zn. 4 edges/warp, 8 lanes/edge.
// ---------------------------------------------------------------------------
__device__ __forceinline__ float dot16(uint4 a, uint4 b) {
    const __half2* ah = (const __half2*)&a;
    const __half2* bh = (const __half2*)&b;
    float s = 0.f;
    #pragma unroll
    for (int i = 0; i < 4; i++) {
        float2 fa = __half22float2(ah[i]);
        float2 fb = __half22float2(bh[i]);
        s += fa.x * fb.x + fa.y * fb.y;
    }
    return s;
}

__global__ __launch_bounds__(256)
void edge_cos_kernel(const int* __restrict__ ei,
                     float* __restrict__ out, int E, int N)
{
    int warp_id = (blockIdx.x * blockDim.x + threadIdx.x) >> 5;
    int lane = threadIdx.x & 31;
    int sub  = lane & 7;
    int eg   = lane >> 3;
    int e = warp_id * 4 + eg;
    bool valid = e < E;
    int ec = valid ? __ldg(ei + e) : 0;
    int er = valid ? __ldg(ei + E + e) : 0;
    ec = min(max(ec, 0), N - 1);
    er = min(max(er, 0), N - 1);

    const uint4* pa = (const uint4*)(g_zn_h + (size_t)ec * H);
    const uint4* pb = (const uint4*)(g_zn_h + (size_t)er * H);

    uint4 a0 = pa[sub],     b0 = pb[sub];
    uint4 a1 = pa[sub + 8], b1 = pb[sub + 8];

    float s = dot16(a0, b0) + dot16(a1, b1);

    s += __shfl_xor_sync(0xFFFFFFFFu, s, 4);
    s += __shfl_xor_sync(0xFFFFFFFFu, s, 2);
    s += __shfl_xor_sync(0xFFFFFFFFu, s, 1);
    if (sub == 0 && valid) out[e] = s;
}

// ---------------------------------------------------------------------------
extern "C" void kernel_launch(void* const* d_in, const int* in_sizes, int n_in,
                              void* d_out, int out_size)
{
    const float* emb = (const float*)d_in[0];
    const int*   ei  = (const int*)d_in[1];
    const float* W1  = (const float*)d_in[2];
    const float* b1  = (const float*)d_in[3];
    const float* W2  = (const float*)d_in[4];
    const float* b2  = (const float*)d_in[5];
    float* out = (float*)d_out;

    int N = in_sizes[0] / H;
    int E = in_sizes[1] / 2;
    int n_tiles = (N + 31) / 32;
    int gridA = n_tiles < 148 ? n_tiles : 148;

    mlp_phase<0><<<gridA, 512>>>(emb, W1, b1, N, n_tiles);
    mlp_phase<1><<<gridA, 512>>>(emb, W2, b2, N, n_tiles);

    int warps  = (E + 3) / 4;
    int blocks = (warps + 7) / 8;
    edge_cos_kernel<<<blocks, 256>>>(ei, out, E, N);
}

// round 14
// speedup vs baseline: 1.9896x; 1.0474x over previous
#include <cuda_runtime.h>
#include <cuda_fp16.h>
#include <cstdint>

#define H 128
#define MAX_N 50048
#define TILE 64

__device__ __half g_zn_h[(size_t)MAX_N * H];  // normalized layer-2 output (fp16)
__device__ __half g_h_h[(size_t)MAX_N * H];   // layer-1 activations (fp16)

// m16n8k16 fp16 MMA, fp32 accumulate in-place.
__device__ __forceinline__ void mma16(float* d, const uint32_t* a, const uint32_t* b) {
    asm volatile("mma.sync.aligned.m16n8k16.row.col.f32.f16.f16.f32 "
        "{%0,%1,%2,%3}, {%4,%5,%6,%7}, {%8,%9}, {%0,%1,%2,%3};"
        : "+f"(d[0]), "+f"(d[1]), "+f"(d[2]), "+f"(d[3])
        : "r"(a[0]), "r"(a[1]), "r"(a[2]), "r"(a[3]), "r"(b[0]), "r"(b[1]));
}

__device__ __forceinline__ uint32_t packh2(__half lo, __half hi) {
    __half2 h = __halves2half2(lo, hi);
    return *(uint32_t*)&h;
}

__device__ __forceinline__ void cpasync16(uint32_t dst, const void* src, int srcsize) {
    asm volatile("cp.async.ca.shared.global [%0], [%1], 16, %2;"
                 :: "r"(dst), "l"(src), "r"(srcsize) : "memory");
}
#define CP_COMMIT() asm volatile("cp.async.commit_group;" ::: "memory")
#define CP_WAIT0()  asm volatile("cp.async.wait_group 0;" ::: "memory")

// smem layout (bytes)
// MODE0: [0,33792) xraw fp32 64x132 | [33792,51200) xsH | [51200,68608) xsL
// MODE1: [0,17408) xsH buf0 | [17408,34816) xsH buf1 | [34816,35072) ssbuf
#define XRAW_PITCH_B 528            // 132 floats
#define XS_PITCH_W   68             // uint32 words per row (136 halves)
#define XS_PITCH_B   272
#define XS_BYTES     17408
#define SMEM0        68608
#define SMEM1        35072

// ---------------------------------------------------------------------------
// MODE 0: h = ELU(emb@W1^T + b1) -> g_h_h (fp16).  3-pass fp16 split
//         (xH*wH + xL*wH + xH*wL), emb split once/CTA into xsH/xsL.
// MODE 1: zn = rownorm(h@W2^T + b2) -> g_zn_h.  h is EXACT fp16 -> 2 passes
//         (xH*wH + xH*wL); cp.async lands h directly in MMA layout (no split).
// 512 thr / 16 warps; 64-row tile = 2 sequential 32-row sub-tiles; cp.async
// prefetch of tile t+1 overlaps tile t mainloop.
// ---------------------------------------------------------------------------
template<int MODE>
__global__ __launch_bounds__(512, 1)
void mlp_phase(const float* __restrict__ Xf, const float* __restrict__ W,
               const float* __restrict__ bias, int N, int n_tiles)
{
    extern __shared__ char smem[];
    float*    xraw = (float*)smem;
    uint32_t* xsH  = (MODE == 0) ? (uint32_t*)(smem + 33792) : (uint32_t*)smem;
    uint32_t* xsL  = (uint32_t*)(smem + 51200);
    float*    ssbuf = (float*)(smem + 34816);
    const uint32_t sbase = (uint32_t)__cvta_generic_to_shared(smem);

    const int tid  = threadIdx.x;
    const int warp = tid >> 5, lane = tid & 31;
    const int qr = lane >> 2, qc = lane & 3;
    const int rh = warp >> 3, cw = warp & 7;

    // ---- B fragments: warp's 16 cols, fp16 hi/lo, in registers ----
    uint32_t bH[8][2][2], bL[8][2][2];
    #pragma unroll
    for (int kt = 0; kt < 8; kt++)
        #pragma unroll
        for (int nt = 0; nt < 2; nt++) {
            const int n = cw * 16 + nt * 8 + qr;
            const float* wp = W + n * H + kt * 16 + 2 * qc;
            float w0 = __ldg(wp),     w1 = __ldg(wp + 1);
            float w2 = __ldg(wp + 8), w3 = __ldg(wp + 9);
            __half h0 = __float2half_rn(w0), h1 = __float2half_rn(w1);
            __half h2 = __float2half_rn(w2), h3 = __float2half_rn(w3);
            bH[kt][nt][0] = packh2(h0, h1);
            bH[kt][nt][1] = packh2(h2, h3);
            bL[kt][nt][0] = packh2(__float2half_rn(w0 - __half2float(h0)),
                                   __float2half_rn(w1 - __half2float(h1)));
            bL[kt][nt][1] = packh2(__float2half_rn(w2 - __half2float(h2)),
                                   __float2half_rn(w3 - __half2float(h3)));
        }
    const float2 bv0 = __ldg((const float2*)(bias + cw * 16 + 2 * qc));
    const float2 bv1 = __ldg((const float2*)(bias + cw * 16 + 8 + 2 * qc));

    // ---- prefetch (cp.async, no registers) ----
    auto prefetch = [&](int t, int p) {
        const int row0 = t * TILE;
        if (MODE == 0) {
            #pragma unroll
            for (int j = 0; j < 4; j++) {
                int id = tid + j * 512;
                int r = id >> 5, c = id & 31;
                int row = row0 + r;
                bool v = row < N;
                const float* src = Xf + (size_t)(v ? row : 0) * H + c * 4;
                cpasync16(sbase + r * XRAW_PITCH_B + c * 16, src, v ? 16 : 0);
            }
        } else {
            #pragma unroll
            for (int j = 0; j < 2; j++) {
                int id = tid + j * 512;
                int r = id >> 4, c = id & 15;
                int row = row0 + r;
                bool v = row < N;
                const __half* src = g_h_h + (size_t)(v ? row : 0) * H + c * 8;
                cpasync16(sbase + p * XS_BYTES + r * XS_PITCH_B + c * 16, src, v ? 16 : 0);
            }
        }
        CP_COMMIT();
    };

    int tile = blockIdx.x;
    int p = 0;
    if (tile < n_tiles) prefetch(tile, 0);

    for (; tile < n_tiles; tile += gridDim.x) {
        const int row0 = tile * TILE;
        const int nxt = tile + gridDim.x;
        CP_WAIT0();
        __syncthreads();                       // data visible; prev readers done

        if (MODE == 0) {
            // split xraw -> fp16 hi/lo
            #pragma unroll
            for (int j = 0; j < 4; j++) {
                int id = tid + j * 512;
                int r = id >> 5, c4 = id & 31;
                float4 v = *(float4*)(xraw + r * 132 + c4 * 4);
                __half h0 = __float2half_rn(v.x), h1 = __float2half_rn(v.y);
                __half h2 = __float2half_rn(v.z), h3 = __float2half_rn(v.w);
                uint32_t* dh = xsH + r * XS_PITCH_W + c4 * 2;
                uint32_t* dl = xsL + r * XS_PITCH_W + c4 * 2;
                dh[0] = packh2(h0, h1); dh[1] = packh2(h2, h3);
                dl[0] = packh2(__float2half_rn(v.x - __half2float(h0)),
                               __float2half_rn(v.y - __half2float(h1)));
                dl[1] = packh2(__float2half_rn(v.z - __half2float(h2)),
                               __float2half_rn(v.w - __half2float(h3)));
            }
            __syncthreads();
            if (nxt < n_tiles) prefetch(nxt, 0);   // xraw free now
        } else {
            if (tid < 64) ssbuf[tid] = 0.f;
            __syncthreads();
            if (nxt < n_tiles) prefetch(nxt, p ^ 1);
        }

        #pragma unroll
        for (int s = 0; s < 2; s++) {
            float aA0[4] = {0,0,0,0}, aA1[4] = {0,0,0,0};
            float aB0[4] = {0,0,0,0}, aB1[4] = {0,0,0,0};
            float aC0[4] = {0,0,0,0}, aC1[4] = {0,0,0,0};
            const int rbase = s * 32 + rh * 16 + qr;
            const uint32_t* hb = (MODE == 0) ? xsH : xsH + p * (XS_BYTES / 4);
            const uint32_t* hlo = hb + rbase * XS_PITCH_W + qc;
            const uint32_t* hhi = hlo + 8 * XS_PITCH_W;
            const uint32_t* llo = xsL + rbase * XS_PITCH_W + qc;
            const uint32_t* lhi = llo + 8 * XS_PITCH_W;

            #pragma unroll
            for (int kt = 0; kt < 8; kt++) {
                uint32_t aH[4];
                aH[0] = hlo[kt * 8];     aH[1] = hhi[kt * 8];
                aH[2] = hlo[kt * 8 + 4]; aH[3] = hhi[kt * 8 + 4];
                mma16(aA0, aH, bH[kt][0]);  mma16(aA1, aH, bH[kt][1]);
                if (MODE == 0) {
                    uint32_t aL[4];
                    aL[0] = llo[kt * 8];     aL[1] = lhi[kt * 8];
                    aL[2] = llo[kt * 8 + 4]; aL[3] = lhi[kt * 8 + 4];
                    mma16(aB0, aL, bH[kt][0]);  mma16(aB1, aL, bH[kt][1]);
                }
                mma16(aC0, aH, bL[kt][0]);  mma16(aC1, aH, bL[kt][1]);
            }

            const int r_lo = row0 + rbase, r_hi = r_lo + 8;
            const int c0 = cw * 16 + 2 * qc, c1 = c0 + 8;
            float z00 = aA0[0] + aC0[0] + bv0.x;
            float z01 = aA0[1] + aC0[1] + bv0.y;
            float z02 = aA0[2] + aC0[2] + bv0.x;
            float z03 = aA0[3] + aC0[3] + bv0.y;
            float z10 = aA1[0] + aC1[0] + bv1.x;
            float z11 = aA1[1] + aC1[1] + bv1.y;
            float z12 = aA1[2] + aC1[2] + bv1.x;
            float z13 = aA1[3] + aC1[3] + bv1.y;
            if (MODE == 0) {
                z00 += aB0[0]; z01 += aB0[1]; z02 += aB0[2]; z03 += aB0[3];
                z10 += aB1[0]; z11 += aB1[1]; z12 += aB1[2]; z13 += aB1[3];
            }

            if (MODE == 0) {
                if (r_lo < N) {
                    float e0 = z00 > 0.f ? z00 : expm1f(z00);
                    float e1 = z01 > 0.f ? z01 : expm1f(z01);
                    float e2 = z10 > 0.f ? z10 : expm1f(z10);
                    float e3 = z11 > 0.f ? z11 : expm1f(z11);
                    *(__half2*)(g_h_h + (size_t)r_lo * H + c0) = __floats2half2_rn(e0, e1);
                    *(__half2*)(g_h_h + (size_t)r_lo * H + c1) = __floats2half2_rn(e2, e3);
                }
                if (r_hi < N) {
                    float e0 = z02 > 0.f ? z02 : expm1f(z02);
                    float e1 = z03 > 0.f ? z03 : expm1f(z03);
                    float e2 = z12 > 0.f ? z12 : expm1f(z12);
                    float e3 = z13 > 0.f ? z13 : expm1f(z13);
                    *(__half2*)(g_h_h + (size_t)r_hi * H + c0) = __floats2half2_rn(e0, e1);
                    *(__half2*)(g_h_h + (size_t)r_hi * H + c1) = __floats2half2_rn(e2, e3);
                }
            } else {
                float s_lo = z00*z00 + z01*z01 + z10*z10 + z11*z11;
                float s_hi = z02*z02 + z03*z03 + z12*z12 + z13*z13;
                s_lo += __shfl_xor_sync(0xFFFFFFFFu, s_lo, 1);
                s_lo += __shfl_xor_sync(0xFFFFFFFFu, s_lo, 2);
                s_hi += __shfl_xor_sync(0xFFFFFFFFu, s_hi, 1);
                s_hi += __shfl_xor_sync(0xFFFFFFFFu, s_hi, 2);
                if (qc == 0) {
                    atomicAdd(&ssbuf[rbase], s_lo);
                    atomicAdd(&ssbuf[rbase + 8], s_hi);
                }
                __syncthreads();
                float inv_lo = 1.0f / fmaxf(sqrtf(ssbuf[rbase]),     1e-8f);
                float inv_hi = 1.0f / fmaxf(sqrtf(ssbuf[rbase + 8]), 1e-8f);
                if (r_lo < N) {
                    *(__half2*)(g_zn_h + (size_t)r_lo * H + c0) =
                        __floats2half2_rn(z00 * inv_lo, z01 * inv_lo);
                    *(__half2*)(g_zn_h + (size_t)r_lo * H + c1) =
                        __floats2half2_rn(z10 * inv_lo, z11 * inv_lo);
                }
                if (r_hi < N) {
                    *(__half2*)(g_zn_h + (size_t)r_hi * H + c0) =
                        __floats2half2_rn(z02 * inv_hi, z03 * inv_hi);
                    *(__half2*)(g_zn_h + (size_t)r_hi * H + c1) =
                        __floats2half2_rn(z12 * inv_hi, z13 * inv_hi);
                }
            }
        }
        if (MODE == 1) p ^= 1;
    }
}

// ---------------------------------------------------------------------------
// Kernel B: per-edge cosine over fp16 zn. 4 edges/warp, 8 lanes/edge.
// ---------------------------------------------------------------------------
__device__ __forceinline__ float dot16(uint4 a, uint4 b) {
    const __half2* ah = (const __half2*)&a;
    const __half2* bh = (const __half2*)&b;
    float s = 0.f;
    #pragma unroll
    for (int i = 0; i < 4; i++) {
        float2 fa = __half22float2(ah[i]);
        float2 fb = __half22float2(bh[i]);
        s += fa.x * fb.x + fa.y * fb.y;
    }
    return s;
}

__global__ __launch_bounds__(256)
void edge_cos_kernel(const int* __restrict__ ei,
                     float* __restrict__ out, int E, int N)
{
    int warp_id = (blockIdx.x * blockDim.x + threadIdx.x) >> 5;
    int lane = threadIdx.x & 31;
    int sub  = lane & 7;
    int eg   = lane >> 3;
    int e = warp_id * 4 + eg;
    bool valid = e < E;
    int ec = valid ? __ldg(ei + e) : 0;
    int er = valid ? __ldg(ei + E + e) : 0;
    ec = min(max(ec, 0), N - 1);
    er = min(max(er, 0), N - 1);

    const uint4* pa = (const uint4*)(g_zn_h + (size_t)ec * H);
    const uint4* pb = (const uint4*)(g_zn_h + (size_t)er * H);

    uint4 a0 = pa[sub],     b0 = pb[sub];
    uint4 a1 = pa[sub + 8], b1 = pb[sub + 8];

    float s = dot16(a0, b0) + dot16(a1, b1);

    s += __shfl_xor_sync(0xFFFFFFFFu, s, 4);
    s += __shfl_xor_sync(0xFFFFFFFFu, s, 2);
    s += __shfl_xor_sync(0xFFFFFFFFu, s, 1);
    if (sub == 0 && valid) out[e] = s;
}

// ---------------------------------------------------------------------------
extern "C" void kernel_launch(void* const* d_in, const int* in_sizes, int n_in,
                              void* d_out, int out_size)
{
    const float* emb = (const float*)d_in[0];
    const int*   ei  = (const int*)d_in[1];
    const float* W1  = (const float*)d_in[2];
    const float* b1  = (const float*)d_in[3];
    const float* W2  = (const float*)d_in[4];
    const float* b2  = (const float*)d_in[5];
    float* out = (float*)d_out;

    int N = in_sizes[0] / H;
    int E = in_sizes[1] / 2;
    int n_tiles = (N + TILE - 1) / TILE;
    int gridA = n_tiles < 148 ? n_tiles : 148;

    cudaFuncSetAttribute(mlp_phase<0>, cudaFuncAttributeMaxDynamicSharedMemorySize, SMEM0);
    cudaFuncSetAttribute(mlp_phase<1>, cudaFuncAttributeMaxDynamicSharedMemorySize, SMEM1);

    mlp_phase<0><<<gridA, 512, SMEM0>>>(emb, W1, b1, N, n_tiles);
    mlp_phase<1><<<gridA, 512, SMEM1>>>(emb, W2, b2, N, n_tiles);

    int warps  = (E + 3) / 4;
    int blocks = (warps + 7) / 8;
    edge_cos_kernel<<<blocks, 256>>>(ei, out, E, N);
}

// round 17
// speedup vs baseline: 2.0821x; 1.0465x over previous
#include <cuda_runtime.h>
#include <cuda_fp16.h>
#include <cstdint>

#define H 128
#define MAX_N 50048
#define TILE 64

__device__ __half g_zn_h[(size_t)MAX_N * H];  // normalized layer-2 output (fp16)
__device__ __half g_h_h[(size_t)MAX_N * H];   // layer-1 activations (fp16)

// m16n8k16 fp16 MMA, fp32 accumulate in-place.
__device__ __forceinline__ void mma16(float* d, const uint32_t* a, const uint32_t* b) {
    asm volatile("mma.sync.aligned.m16n8k16.row.col.f32.f16.f16.f32 "
        "{%0,%1,%2,%3}, {%4,%5,%6,%7}, {%8,%9}, {%0,%1,%2,%3};"
        : "+f"(d[0]), "+f"(d[1]), "+f"(d[2]), "+f"(d[3])
        : "r"(a[0]), "r"(a[1]), "r"(a[2]), "r"(a[3]), "r"(b[0]), "r"(b[1]));
}

__device__ __forceinline__ void ldsm4(uint32_t* r, uint32_t addr) {
    asm volatile("ldmatrix.sync.aligned.m8n8.x4.shared.b16 {%0,%1,%2,%3}, [%4];"
        : "=r"(r[0]), "=r"(r[1]), "=r"(r[2]), "=r"(r[3]) : "r"(addr));
}

__device__ __forceinline__ uint32_t packh2(__half lo, __half hi) {
    __half2 h = __halves2half2(lo, hi);
    return *(uint32_t*)&h;
}

__device__ __forceinline__ void cpasync16(uint32_t dst, const void* src, int srcsize) {
    asm volatile("cp.async.ca.shared.global [%0], [%1], 16, %2;"
                 :: "r"(dst), "l"(src), "r"(srcsize) : "memory");
}
#define CP_COMMIT() asm volatile("cp.async.commit_group;" ::: "memory")
#define CP_WAIT0()  asm volatile("cp.async.wait_group 0;" ::: "memory")

// smem layout (bytes) — IDENTICAL to the R14 (last passing) kernel
// MODE0: xraw fp32 64x132 @0 | xsH @33792 | xsL @51200   (68608)
// MODE1: xsH buf0 @0 | buf1 @17408 | ssbuf @34816        (35072)
#define XRAW_PITCH_B 528
#define XSH0         33792
#define XSL0         51200
#define XS_PITCH_W   68
#define XS_PITCH_B   272
#define XS_BYTES     17408
#define SMEM0        68608
#define SMEM1        35072

// ---------------------------------------------------------------------------
// MODE 0: h = ELU(emb@W1^T + b1) -> g_h_h.  3-pass fp16 split
//         (xH*wH + xL*wH + xH*wL); per-tile split once/CTA; ldmatrix A loads.
// MODE 1: zn = rownorm(h@W2^T + b2) -> g_zn_h.  h exact fp16 -> 2 passes;
//         cp.async lands h in MMA layout; 1 ldmatrix + 2 MMA per k-step.
// 512 thr / 16 warps; 64-row tile (2x32 sub-tiles); cp.async prefetch of
// tile t+1 overlaps tile t mainloop (mode0: after split; mode1: dbl-buffer).
// ---------------------------------------------------------------------------
template<int MODE>
__global__ __launch_bounds__(512, 1)
void mlp_phase(const float* __restrict__ Xf, const float* __restrict__ W,
               const float* __restrict__ bias, int N, int n_tiles)
{
    extern __shared__ char smem[];
    float*    xraw = (float*)smem;
    uint32_t* xsH  = (MODE == 0) ? (uint32_t*)(smem + XSH0) : (uint32_t*)smem;
    uint32_t* xsL  = (uint32_t*)(smem + XSL0);
    float*    ssbuf = (float*)(smem + 34816);
    const uint32_t sbase = (uint32_t)__cvta_generic_to_shared(smem);

    const int tid  = threadIdx.x;
    const int warp = tid >> 5, lane = tid & 31;
    const int qr = lane >> 2, qc = lane & 3;
    const int rh = warp >> 3, cw = warp & 7;
    const int r_in = lane & 7, hi8 = (lane >> 3) & 1, kh = lane >> 4;

    // ---- B fragments: warp's 16 cols, fp16 hi/lo, in registers ----
    uint32_t bH[8][2][2], bL[8][2][2];
    #pragma unroll
    for (int kt = 0; kt < 8; kt++)
        #pragma unroll
        for (int nt = 0; nt < 2; nt++) {
            const int n = cw * 16 + nt * 8 + qr;
            const float* wp = W + n * H + kt * 16 + 2 * qc;
            float w0 = __ldg(wp),     w1 = __ldg(wp + 1);
            float w2 = __ldg(wp + 8), w3 = __ldg(wp + 9);
            __half h0 = __float2half_rn(w0), h1 = __float2half_rn(w1);
            __half h2 = __float2half_rn(w2), h3 = __float2half_rn(w3);
            bH[kt][nt][0] = packh2(h0, h1);
            bH[kt][nt][1] = packh2(h2, h3);
            bL[kt][nt][0] = packh2(__float2half_rn(w0 - __half2float(h0)),
                                   __float2half_rn(w1 - __half2float(h1)));
            bL[kt][nt][1] = packh2(__float2half_rn(w2 - __half2float(h2)),
                                   __float2half_rn(w3 - __half2float(h3)));
        }
    const float2 bv0 = __ldg((const float2*)(bias + cw * 16 + 2 * qc));
    const float2 bv1 = __ldg((const float2*)(bias + cw * 16 + 8 + 2 * qc));

    // ---- prefetch (cp.async, no registers) ----
    auto prefetch = [&](int t, int p) {
        const int row0 = t * TILE;
        if (MODE == 0) {
            #pragma unroll
            for (int j = 0; j < 4; j++) {
                int id = tid + j * 512;
                int r = id >> 5, c = id & 31;
                int row = row0 + r;
                bool v = row < N;
                const float* src = Xf + (size_t)(v ? row : 0) * H + c * 4;
                cpasync16(sbase + r * XRAW_PITCH_B + c * 16, src, v ? 16 : 0);
            }
        } else {
            #pragma unroll
            for (int j = 0; j < 2; j++) {
                int id = tid + j * 512;
                int r = id >> 4, c = id & 15;
                int row = row0 + r;
                bool v = row < N;
                const __half* src = g_h_h + (size_t)(v ? row : 0) * H + c * 8;
                cpasync16(sbase + p * XS_BYTES + r * XS_PITCH_B + c * 16, src, v ? 16 : 0);
            }
        }
        CP_COMMIT();
    };

    int tile = blockIdx.x;
    int p = 0;
    if (tile < n_tiles) prefetch(tile, 0);

    for (; tile < n_tiles; tile += gridDim.x) {
        const int row0 = tile * TILE;
        const int nxt = tile + gridDim.x;
        CP_WAIT0();
        __syncthreads();                       // data visible; prev readers done

        if (MODE == 0) {
            // split xraw -> fp16 hi/lo
            #pragma unroll
            for (int j = 0; j < 4; j++) {
                int id = tid + j * 512;
                int r = id >> 5, c4 = id & 31;
                float4 v = *(float4*)(xraw + r * 132 + c4 * 4);
                __half h0 = __float2half_rn(v.x), h1 = __float2half_rn(v.y);
                __half h2 = __float2half_rn(v.z), h3 = __float2half_rn(v.w);
                uint32_t* dh = xsH + r * XS_PITCH_W + c4 * 2;
                uint32_t* dl = xsL + r * XS_PITCH_W + c4 * 2;
                dh[0] = packh2(h0, h1); dh[1] = packh2(h2, h3);
                dl[0] = packh2(__float2half_rn(v.x - __half2float(h0)),
                               __float2half_rn(v.y - __half2float(h1)));
                dl[1] = packh2(__float2half_rn(v.z - __half2float(h2)),
                               __float2half_rn(v.w - __half2float(h3)));
            }
            __syncthreads();
            if (nxt < n_tiles) prefetch(nxt, 0);   // xraw free now
        } else {
            if (tid < 64) ssbuf[tid] = 0.f;
            __syncthreads();
            if (nxt < n_tiles) prefetch(nxt, p ^ 1);
        }

        #pragma unroll
        for (int s = 0; s < 2; s++) {
            float aA0[4] = {0,0,0,0}, aA1[4] = {0,0,0,0};
            float aB0[4] = {0,0,0,0}, aB1[4] = {0,0,0,0};
            float aC0[4] = {0,0,0,0}, aC1[4] = {0,0,0,0};
            const int rbase0 = s * 32 + rh * 16;
            const int ldrow = rbase0 + r_in + hi8 * 8;
            uint32_t aHaddr, aLaddr = 0;
            if (MODE == 0) {
                aHaddr = sbase + XSH0 + ldrow * XS_PITCH_B + kh * 16;
                aLaddr = sbase + XSL0 + ldrow * XS_PITCH_B + kh * 16;
            } else {
                aHaddr = sbase + p * XS_BYTES + ldrow * XS_PITCH_B + kh * 16;
            }

            #pragma unroll
            for (int kt = 0; kt < 8; kt++) {
                uint32_t aH[4];
                ldsm4(aH, aHaddr + kt * 32);
                mma16(aA0, aH, bH[kt][0]);  mma16(aA1, aH, bH[kt][1]);
                if (MODE == 0) {
                    uint32_t aL[4];
                    ldsm4(aL, aLaddr + kt * 32);
                    mma16(aB0, aL, bH[kt][0]);  mma16(aB1, aL, bH[kt][1]);
                }
                mma16(aC0, aH, bL[kt][0]);  mma16(aC1, aH, bL[kt][1]);
            }

            const int rbase = rbase0 + qr;
            const int r_lo = row0 + rbase, r_hi = r_lo + 8;
            const int c0 = cw * 16 + 2 * qc, c1 = c0 + 8;
            float z00 = aA0[0] + aC0[0] + bv0.x;
            float z01 = aA0[1] + aC0[1] + bv0.y;
            float z02 = aA0[2] + aC0[2] + bv0.x;
            float z03 = aA0[3] + aC0[3] + bv0.y;
            float z10 = aA1[0] + aC1[0] + bv1.x;
            float z11 = aA1[1] + aC1[1] + bv1.y;
            float z12 = aA1[2] + aC1[2] + bv1.x;
            float z13 = aA1[3] + aC1[3] + bv1.y;
            if (MODE == 0) {
                z00 += aB0[0]; z01 += aB0[1]; z02 += aB0[2]; z03 += aB0[3];
                z10 += aB1[0]; z11 += aB1[1]; z12 += aB1[2]; z13 += aB1[3];
            }

            if (MODE == 0) {
                if (r_lo < N) {
                    float e0 = z00 > 0.f ? z00 : expm1f(z00);
                    float e1 = z01 > 0.f ? z01 : expm1f(z01);
                    float e2 = z10 > 0.f ? z10 : expm1f(z10);
                    float e3 = z11 > 0.f ? z11 : expm1f(z11);
                    *(__half2*)(g_h_h + (size_t)r_lo * H + c0) = __floats2half2_rn(e0, e1);
                    *(__half2*)(g_h_h + (size_t)r_lo * H + c1) = __floats2half2_rn(e2, e3);
                }
                if (r_hi < N) {
                    float e0 = z02 > 0.f ? z02 : expm1f(z02);
                    float e1 = z03 > 0.f ? z03 : expm1f(z03);
                    float e2 = z12 > 0.f ? z12 : expm1f(z12);
                    float e3 = z13 > 0.f ? z13 : expm1f(z13);
                    *(__half2*)(g_h_h + (size_t)r_hi * H + c0) = __floats2half2_rn(e0, e1);
                    *(__half2*)(g_h_h + (size_t)r_hi * H + c1) = __floats2half2_rn(e2, e3);
                }
            } else {
                float s_lo = z00*z00 + z01*z01 + z10*z10 + z11*z11;
                float s_hi = z02*z02 + z03*z03 + z12*z12 + z13*z13;
                s_lo += __shfl_xor_sync(0xFFFFFFFFu, s_lo, 1);
                s_lo += __shfl_xor_sync(0xFFFFFFFFu, s_lo, 2);
                s_hi += __shfl_xor_sync(0xFFFFFFFFu, s_hi, 1);
                s_hi += __shfl_xor_sync(0xFFFFFFFFu, s_hi, 2);
                if (qc == 0) {
                    atomicAdd(&ssbuf[rbase], s_lo);
                    atomicAdd(&ssbuf[rbase + 8], s_hi);
                }
                __syncthreads();
                float inv_lo = 1.0f / fmaxf(sqrtf(ssbuf[rbase]),     1e-8f);
                float inv_hi = 1.0f / fmaxf(sqrtf(ssbuf[rbase + 8]), 1e-8f);
                if (r_lo < N) {
                    *(__half2*)(g_zn_h + (size_t)r_lo * H + c0) =
                        __floats2half2_rn(z00 * inv_lo, z01 * inv_lo);
                    *(__half2*)(g_zn_h + (size_t)r_lo * H + c1) =
                        __floats2half2_rn(z10 * inv_lo, z11 * inv_lo);
                }
                if (r_hi < N) {
                    *(__half2*)(g_zn_h + (size_t)r_hi * H + c0) =
                        __floats2half2_rn(z02 * inv_hi, z03 * inv_hi);
                    *(__half2*)(g_zn_h + (size_t)r_hi * H + c1) =
                        __floats2half2_rn(z12 * inv_hi, z13 * inv_hi);
                }
            }
        }
        if (MODE == 1) p ^= 1;
    }
}

// ---------------------------------------------------------------------------
// Kernel B: per-edge cosine over fp16 zn. 4 edges/warp, 8 lanes/edge.
// ---------------------------------------------------------------------------
__device__ __forceinline__ float dot16(uint4 a, uint4 b) {
    const __half2* ah = (const __half2*)&a;
    const __half2* bh = (const __half2*)&b;
    float s = 0.f;
    #pragma unroll
    for (int i = 0; i < 4; i++) {
        float2 fa = __half22float2(ah[i]);
        float2 fb = __half22float2(bh[i]);
        s += fa.x * fb.x + fa.y * fb.y;
    }
    return s;
}

__global__ __launch_bounds__(256)
void edge_cos_kernel(const int* __restrict__ ei,
                     float* __restrict__ out, int E, int N)
{
    int warp_id = (blockIdx.x * blockDim.x + threadIdx.x) >> 5;
    int lane = threadIdx.x & 31;
    int sub  = lane & 7;
    int eg   = lane >> 3;
    int e = warp_id * 4 + eg;
    bool valid = e < E;
    int ec = valid ? __ldg(ei + e) : 0;
    int er = valid ? __ldg(ei + E + e) : 0;
    ec = min(max(ec, 0), N - 1);
    er = min(max(er, 0), N - 1);

    const uint4* pa = (const uint4*)(g_zn_h + (size_t)ec * H);
    const uint4* pb = (const uint4*)(g_zn_h + (size_t)er * H);

    uint4 a0 = pa[sub],     b0 = pb[sub];
    uint4 a1 = pa[sub + 8], b1 = pb[sub + 8];

    float s = dot16(a0, b0) + dot16(a1, b1);

    s += __shfl_xor_sync(0xFFFFFFFFu, s, 4);
    s += __shfl_xor_sync(0xFFFFFFFFu, s, 2);
    s += __shfl_xor_sync(0xFFFFFFFFu, s, 1);
    if (sub == 0 && valid) out[e] = s;
}

// ---------------------------------------------------------------------------
extern "C" void kernel_launch(void* const* d_in, const int* in_sizes, int n_in,
                              void* d_out, int out_size)
{
    const float* emb = (const float*)d_in[0];
    const int*   ei  = (const int*)d_in[1];
    const float* W1  = (const float*)d_in[2];
    const float* b1  = (const float*)d_in[3];
    const float* W2  = (const float*)d_in[4];
    const float* b2  = (const float*)d_in[5];
    float* out = (float*)d_out;

    int N = in_sizes[0] / H;
    int E = in_sizes[1] / 2;
    int n_tiles = (N + TILE - 1) / TILE;
    int gridA = n_tiles < 148 ? n_tiles : 148;

    cudaFuncSetAttribute(mlp_phase<0>, cudaFuncAttributeMaxDynamicSharedMemorySize, SMEM0);
    cudaFuncSetAttribute(mlp_phase<1>, cudaFuncAttributeMaxDynamicSharedMemorySize, SMEM1);

    mlp_phase<0><<<gridA, 512, SMEM0>>>(emb, W1, b1, N, n_tiles);
    mlp_phase<1><<<gridA, 512, SMEM1>>>(emb, W2, b2, N, n_tiles);

    int warps  = (E + 3) / 4;
    int blocks = (warps + 7) / 8;
    edge_cos_kernel<<<blocks, 256>>>(ei, out, E, N);
}